// round 16
// baseline (speedup 1.0000x reference)
#include <cuda_runtime.h>

// Problem constants: T=1024, B=64, I=512, H=512, 3H=1536
#define NCTA 128
#define NTEAMS 8        // 8 teams x 16 CTAs; team tau owns b in {tau, tau+8, ..., tau+56}
#define NTHR 768        // 24 warps = 2 groups x 12 warps (independent pipelines)

// ---------------- device-global scratch (no allocation allowed) ----------------
__device__ float g_gx[100663296];                        // [1024*64, 1536] input gate pre-acts
__device__ __align__(16) float g_hB[2][NTEAMS][2][256][8]; // [buf][team][grp][kp][4b x 2par]
__device__ unsigned int g_flagA[NCTA];                   // per-CTA publish counters, group A
__device__ unsigned int g_flagB[NCTA];                   // per-CTA publish counters, group B

// ---------------- f32x2 packed-math helpers (Blackwell, PTX-only path) ----------
__device__ __forceinline__ void ffma2(unsigned long long &acc, unsigned long long a,
                                      unsigned long long b) {
    asm("fma.rn.f32x2 %0, %1, %2, %0;" : "+l"(acc) : "l"(a), "l"(b));
}
__device__ __forceinline__ unsigned long long dup2(float a) {
    unsigned long long r; asm("mov.b64 %0, {%1, %1};" : "=l"(r) : "f"(a)); return r;
}
__device__ __forceinline__ unsigned long long pack2(float lo, float hi) {
    unsigned long long r; asm("mov.b64 %0, {%1, %2};" : "=l"(r) : "f"(lo), "f"(hi)); return r;
}
__device__ __forceinline__ float sum2(unsigned long long v) {
    float lo, hi; asm("mov.b64 {%0, %1}, %2;" : "=f"(lo), "=f"(hi) : "l"(v)); return lo + hi;
}
__device__ __forceinline__ float2 unpack2(unsigned long long v) {
    float2 f; asm("mov.b64 {%0, %1}, %2;" : "=f"(f.x), "=f"(f.y) : "l"(v)); return f;
}

// ---------------- flag primitives (gpu scope, L2-coherent) -----------------------
__device__ __forceinline__ unsigned int ld_acq(const unsigned int* p) {
    unsigned int v;
    asm volatile("ld.acquire.gpu.global.u32 %0, [%1];" : "=r"(v) : "l"(p) : "memory");
    return v;
}
__device__ __forceinline__ unsigned int ld_rlx(const unsigned int* p) {
    unsigned int v;
    asm volatile("ld.relaxed.gpu.global.u32 %0, [%1];" : "=r"(v) : "l"(p) : "memory");
    return v;
}
__device__ __forceinline__ void st_rel(unsigned int* p, unsigned int v) {
    asm volatile("st.release.gpu.global.u32 [%0], %1;" :: "l"(p), "r"(v) : "memory");
}
__device__ __forceinline__ void bar_sync(int id, int cnt) {
    asm volatile("bar.sync %0, %1;" :: "r"(id), "r"(cnt) : "memory");
}

// ---------------- dynamic SMEM layout (floats) -----------------------------------
#define WP_OFF   0                          // W: [96 rows][512]           (196,608 B)
#define HS_OFF   (96 * 512)                 // hs: [2 grp][256 kp][12 pad] ( 24,576 B)
#define HS_ROW   12
#define HS_GRP   (256 * HS_ROW)
#define RED_OFF  (HS_OFF + 2 * HS_GRP)      // red: [2 grp][2 ks][96][6]   (  9,216 B)
#define RED_GRP  (2 * 96 * 6)
#define LENS_OFF (RED_OFF + 2 * RED_GRP)
#define SMEM_FLOATS (LENS_OFF + 16)
#define SMEM_BYTES  (SMEM_FLOATS * 4)       // 230,464 B (< 232,448 cap)

// =================================================================================
// Kernel A: gx[m][n] = sum_k X[m][k] * W[n][k] + bias[n]  (R14 double-buffered)
// =================================================================================
__global__ __launch_bounds__(256) void gemm_gx(const float* __restrict__ X,
                                               const float* __restrict__ W,
                                               const float* __restrict__ bias) {
    __shared__ __align__(16) float As[2][8][128];
    __shared__ __align__(16) float Bs[2][8][128];
    const int tid = threadIdx.x;
    const int m0 = blockIdx.y * 128;
    const int n0 = blockIdx.x * 128;
    const int tx = tid & 15;
    const int ty = tid >> 4;
    const int lrow = tid >> 1;
    const int lk = (tid & 1) * 4;

    unsigned long long acc[8][4];
#pragma unroll
    for (int i = 0; i < 8; i++)
#pragma unroll
        for (int jp = 0; jp < 4; jp++) acc[i][jp] = 0ull;

    const float* xg = X + (size_t)(m0 + lrow) * 512 + lk;
    const float* wg = W + (size_t)(n0 + lrow) * 512 + lk;

    {
        float4 av = *(const float4*)(xg);
        float4 bv = *(const float4*)(wg);
        As[0][lk + 0][lrow] = av.x; As[0][lk + 1][lrow] = av.y;
        As[0][lk + 2][lrow] = av.z; As[0][lk + 3][lrow] = av.w;
        Bs[0][lk + 0][lrow] = bv.x; Bs[0][lk + 1][lrow] = bv.y;
        Bs[0][lk + 2][lrow] = bv.z; Bs[0][lk + 3][lrow] = bv.w;
    }
    __syncthreads();

    for (int k0 = 0; k0 < 512; k0 += 8) {
        const int buf  = (k0 >> 3) & 1;
        const int nbuf = buf ^ 1;
        const bool more = (k0 + 8) < 512;

        float4 av, bv;
        if (more) {
            av = *(const float4*)(xg + k0 + 8);
            bv = *(const float4*)(wg + k0 + 8);
        }

#pragma unroll
        for (int kk = 0; kk < 8; kk++) {
            float4 a0 = *(const float4*)&As[buf][kk][ty * 8];
            float4 a1 = *(const float4*)&As[buf][kk][ty * 8 + 4];
            float4 b0 = *(const float4*)&Bs[buf][kk][tx * 8];
            float4 b1 = *(const float4*)&Bs[buf][kk][tx * 8 + 4];
            unsigned long long bp0 = pack2(b0.x, b0.y);
            unsigned long long bp1 = pack2(b0.z, b0.w);
            unsigned long long bp2 = pack2(b1.x, b1.y);
            unsigned long long bp3 = pack2(b1.z, b1.w);
            float a[8] = {a0.x, a0.y, a0.z, a0.w, a1.x, a1.y, a1.z, a1.w};
#pragma unroll
            for (int i = 0; i < 8; i++) {
                unsigned long long ad = dup2(a[i]);
                ffma2(acc[i][0], ad, bp0);
                ffma2(acc[i][1], ad, bp1);
                ffma2(acc[i][2], ad, bp2);
                ffma2(acc[i][3], ad, bp3);
            }
        }

        if (more) {
            As[nbuf][lk + 0][lrow] = av.x; As[nbuf][lk + 1][lrow] = av.y;
            As[nbuf][lk + 2][lrow] = av.z; As[nbuf][lk + 3][lrow] = av.w;
            Bs[nbuf][lk + 0][lrow] = bv.x; Bs[nbuf][lk + 1][lrow] = bv.y;
            Bs[nbuf][lk + 2][lrow] = bv.z; Bs[nbuf][lk + 3][lrow] = bv.w;
            __syncthreads();
        }
    }

    float bs[8];
#pragma unroll
    for (int c = 0; c < 8; c++) bs[c] = bias[n0 + tx * 8 + c];
#pragma unroll
    for (int i = 0; i < 8; i++) {
        size_t base = (size_t)(m0 + ty * 8 + i) * 1536 + n0 + tx * 8;
        float2 p0 = unpack2(acc[i][0]);
        float2 p1 = unpack2(acc[i][1]);
        float2 p2 = unpack2(acc[i][2]);
        float2 p3 = unpack2(acc[i][3]);
        float4 o0 = make_float4(p0.x + bs[0], p0.y + bs[1], p1.x + bs[2], p1.y + bs[3]);
        float4 o1 = make_float4(p2.x + bs[4], p2.y + bs[5], p3.x + bs[6], p3.y + bs[7]);
        *(float4*)&g_gx[base]     = o0;
        *(float4*)&g_gx[base + 4] = o1;
    }
}

// =================================================================================
// Kernel B: persistent GRU, 8 teams x 16 CTAs, TWO independent 12-warp pipelines
// per CTA (group A = team-b 0..3, group B = team-b 4..7; independent recurrences).
// Each group: own flags, own named barriers, own hs/red; shares read-only W SMEM.
// Per group step: poll (1 warp) -> bar -> stage 8KB -> bar -> FMA -> bar ->
// gate (4 warps: 32u x 4b) publish + release, while the OTHER group's warps keep
// the SM busy -> sync latency hidden. Group dies at its max length -> bulk
// zero-fill + the surviving group gets the whole SM.
// =================================================================================
__global__ __launch_bounds__(NTHR, 1) void gru_rec(const float* __restrict__ whh,
                                                   const float* __restrict__ bhh,
                                                   const int* __restrict__ lens,
                                                   float* __restrict__ out) {
    extern __shared__ __align__(16) float sm[];
    int* sm_lens = (int*)&sm[LENS_OFF];

    const int tid  = threadIdx.x;
    const int tau  = blockIdx.x >> 4;        // team 0..7
    const int c    = blockIdx.x & 15;        // CTA within team, owns units [32c,32c+32)
    const int wrp  = tid >> 5;
    const int lane = tid & 31;

    // ---- preload W slice (96 rows x 512; row = gate*32 + unit) ----
    for (int idx = tid; idx < 96 * 128; idx += NTHR) {
        int row = idx >> 7;
        int k4  = (idx & 127) << 2;
        int g   = row >> 5;
        int u   = row & 31;
        *(float4*)&sm[WP_OFF + row * 512 + k4] =
            *(const float4*)&whh[(size_t)(g * 512 + 32 * c + u) * 512 + k4];
    }
    if (tid < 8) sm_lens[tid] = lens[8 * tid + tau];

    // h(0) = 0: this CTA's 16 kp x 8 floats, both groups
    if (tid < 256) {
        int grp = tid >> 7;
        int kp  = 16 * c + ((tid >> 3) & 15);
        int f   = tid & 7;
        __stcg(&g_hB[0][tau][grp][kp][f], 0.f);
    }
    const unsigned int FA = ld_rlx(&g_flagA[blockIdx.x]);   // monotonic across replays
    const unsigned int FB = ld_rlx(&g_flagB[blockIdx.x]);
    __syncthreads();
    if (tid == 0) {
        st_rel(&g_flagA[blockIdx.x], FA + 1);               // h(0) published (A)
        st_rel(&g_flagB[blockIdx.x], FB + 1);               // h(0) published (B)
    }

    // -------- group decomposition (NO __syncthreads below this point) --------
    const int grp = wrp / 12;                // pipeline 0 or 1
    const int gw  = wrp - grp * 12;          // warp-in-group 0..11
    const int gl  = gw * 32 + lane;          // group-lane 0..383

    // FMA mapping: rg(6 x 16 rows) x ks(2 x 256 k); lane = q(8) x s(2 row-half) x p(2 b-pair)
    const int rg = gw >> 1;
    const int ks = gw & 1;
    const int q  = lane >> 2;
    const int s  = (lane >> 1) & 1;
    const int p  = lane & 1;
    const int rowbase = rg * 16 + s * 8;

    // gate mapping: first 4 warps of the group = 128 threads = 32 units x 4 group-b
    const bool isgate = (gw < 4);
    const int gu  = gl & 31;                 // unit-in-CTA
    const int gbl = (gl >> 5) & 3;           // group-b 0..3
    const int bglob = 8 * (grp * 4 + gbl) + tau;
    const int j = 32 * c + gu;

    const int  ml = sm_lens[grp * 4];        // group max length (uniform across team)
    const unsigned int Fg = grp ? FB : FA;
    unsigned int* myflag  = grp ? &g_flagB[blockIdx.x] : &g_flagA[blockIdx.x];
    const unsigned int* fp = (grp ? g_flagB : g_flagA) + (tau << 4) + (lane & 15);
    float* hs  = &sm[HS_OFF + grp * HS_GRP];
    float* red = &sm[RED_OFF + grp * RED_GRP];
    const int barG = 2 + grp;                // group barrier (384 threads)
    const int barP = 4 + grp;                // gate publish barrier (128 threads)
    const bool ispoll = (gw == 11);

    float bh_r = 0.f, bh_z = 0.f, bh_n = 0.f;
    int len_b = 0;
    if (isgate) {
        bh_r = bhh[j];
        bh_z = bhh[512 + j];
        bh_n = bhh[1024 + j];
        len_b = sm_lens[grp * 4 + gbl];
    }
    float hreg = 0.f;

    for (int t = 0; t < ml; t++) {
        // gx prefetch for gate threads (consumed ~2 barriers + FMA later)
        float gxr = 0.f, gxz = 0.f, gxn = 0.f;
        if (isgate) {
            const float* gxp = g_gx + (size_t)(t * 64 + bglob) * 1536 + j;
            gxr = gxp[0];
            gxz = gxp[512];
            gxn = gxp[1024];
        }

        // [poll] ONE warp of the group waits for the 16 team CTAs' group flags
        if (ispoll) {
            const unsigned int tgt = Fg + 1 + (unsigned)t;
            while (!__all_sync(0xffffffffu, ld_acq(fp) >= tgt)) {}
        }
        bar_sync(barG, 384);

        // [stage] group h(t): 256 kp x 8 floats = 8KB (coalesced 16B loads)
        for (int sI = gl; sI < 512; sI += 384) {
            int kp = sI >> 1;
            int pt = sI & 1;
            float4 v = __ldcg((const float4*)&g_hB[t & 1][tau][grp][kp][4 * pt]);
            *(float4*)&hs[kp * HS_ROW + 4 * pt] = v;
        }
        bar_sync(barG, 384);

        // [FMA] 8 rows x 32 k x 2 b per lane
        {
            unsigned long long accA[8], accB[8];
#pragma unroll
            for (int r = 0; r < 8; r++) { accA[r] = 0ull; accB[r] = 0ull; }

#pragma unroll
            for (int i = 0; i < 8; i++) {
                int kp1 = ks * 128 + i * 16 + 2 * q;
                ulonglong2 hA = *(const ulonglong2*)&hs[kp1 * HS_ROW + 4 * p];
                ulonglong2 hB2 = *(const ulonglong2*)&hs[(kp1 + 1) * HS_ROW + 4 * p];
#pragma unroll
                for (int r = 0; r < 8; r++) {
                    ulonglong2 wv = *(const ulonglong2*)
                        &sm[WP_OFF + (rowbase + r) * 512 + 2 * kp1];
                    ffma2(accA[r], hA.x, wv.x);
                    ffma2(accA[r], hB2.x, wv.y);
                    ffma2(accB[r], hA.y, wv.x);
                    ffma2(accB[r], hB2.y, wv.y);
                }
            }

            // fold q (xor 4,8,16); lanes 0..3 (q==0; s,p vary) store partials
#pragma unroll
            for (int r = 0; r < 8; r++) {
                float sA = sum2(accA[r]);
                float sB = sum2(accB[r]);
                sA += __shfl_xor_sync(0xffffffffu, sA, 4);
                sB += __shfl_xor_sync(0xffffffffu, sB, 4);
                sA += __shfl_xor_sync(0xffffffffu, sA, 8);
                sB += __shfl_xor_sync(0xffffffffu, sB, 8);
                sA += __shfl_xor_sync(0xffffffffu, sA, 16);
                sB += __shfl_xor_sync(0xffffffffu, sB, 16);
                if (lane < 4)
                    *(float2*)&red[(ks * 96 + rowbase + r) * 6 + 2 * p] =
                        make_float2(sA, sB);
            }
        }
        bar_sync(barG, 384);

        // [gate] 4 warps: 32 units x 4 group-b. Poll warp races ahead to t+1.
        if (isgate) {
            float outv = 0.f;
            if (t < len_b) {
                float ghr = bh_r + red[(gu) * 6 + gbl]        + red[(96 + gu) * 6 + gbl];
                float ghz = bh_z + red[(32 + gu) * 6 + gbl]   + red[(96 + 32 + gu) * 6 + gbl];
                float ghn = bh_n + red[(64 + gu) * 6 + gbl]   + red[(96 + 64 + gu) * 6 + gbl];
                float r = 1.f / (1.f + __expf(-(gxr + ghr)));
                float z = 1.f / (1.f + __expf(-(gxz + ghz)));
                float n = tanhf(gxn + r * ghn);
                hreg = (1.f - z) * n + z * hreg;
                outv = hreg;
            }
            // publish h(t+1) unit-pair via shfl partner (gu, gu^1 share gbl)
            float hpart = __shfl_xor_sync(0xffffffffu, hreg, 1);
            if ((gu & 1) == 0) {
                float2 v = make_float2(hreg, hpart);
                __stcg((float2*)&g_hB[(t + 1) & 1][tau][grp][16 * c + (gu >> 1)][2 * gbl], v);
            }
            bar_sync(barP, 128);
            if (gl == 0) st_rel(myflag, Fg + 2 + (unsigned)t);

            out[(size_t)t * 32768 + bglob * 512 + j] = outv;   // off critical path
        }
    }

    // h_last [1,B,H]: hreg is final (sequences ended at len_b <= ml)
    if (isgate)
        out[(size_t)1024 * 32768 + bglob * 512 + j] = hreg;

    // bulk zero-fill for t in [ml, 1024) over this group's 4 b x 32 units
    {
        const long total = (long)(1024 - ml) * 128;
        for (long idx = gl; idx < total; idx += 384) {
            int tt  = ml + (int)(idx >> 7);
            int rem = (int)(idx & 127);
            int bl  = rem >> 5;
            int uu  = rem & 31;
            out[(size_t)tt * 32768 + (size_t)(8 * (grp * 4 + bl) + tau) * 512 + 32 * c + uu] = 0.f;
        }
    }
}

// =================================================================================
// Inputs (metadata order): x[T,B,I] f32, batch_lengths[B] i32, w_ih[3H,I] f32,
// w_hh[3H,H] f32, b_ih[3H] f32, b_hh[3H] f32.  Output: [T,B,H] then [1,B,H], fp32.
// =================================================================================
extern "C" void kernel_launch(void* const* d_in, const int* in_sizes, int n_in,
                              void* d_out, int out_size) {
    const float* x   = (const float*)d_in[0];
    const int*   len = (const int*)  d_in[1];
    const float* wih = (const float*)d_in[2];
    const float* whh = (const float*)d_in[3];
    const float* bih = (const float*)d_in[4];
    const float* bhh = (const float*)d_in[5];
    float* out = (float*)d_out;

    (void)in_sizes; (void)n_in; (void)out_size;

    cudaFuncSetAttribute(gru_rec, cudaFuncAttributeMaxDynamicSharedMemorySize, SMEM_BYTES);

    gemm_gx<<<dim3(12, 512), 256>>>(x, wih, bih);
    gru_rec<<<NCTA, NTHR, SMEM_BYTES>>>(whh, bhh, len, out);
}